// round 10
// baseline (speedup 1.0000x reference)
#include <cuda_runtime.h>
#include <cuda_bf16.h>
#include <math.h>

#define Nn 1024
#define Dd 1024
#define Gg 16

// Scratch (allocation-free rule: __device__ globals)
__device__ float g_q[Nn * Dd];                 // q[i, g*64+d]
__device__ float g_k[Nn * Dd];                 // k[j, g*64+d]
__device__ float g_v2[Nn * Dd];                // v2T[g*64+o, j]
__device__ float g_aff[(size_t)Nn * Gg * Nn];  // aff[i,g,j] (raw positional bias)

__device__ __forceinline__ unsigned f2tf(float x) {
    unsigned u; asm("cvt.rna.tf32.f32 %0, %1;" : "=r"(u) : "f"(x)); return u;
}
__device__ __forceinline__ void mma_tf32(float* c,
    unsigned a0, unsigned a1, unsigned a2, unsigned a3,
    unsigned b0, unsigned b1) {
    asm volatile(
        "mma.sync.aligned.m16n8k8.row.col.f32.tf32.tf32.f32 "
        "{%0,%1,%2,%3}, {%4,%5,%6,%7}, {%8,%9}, {%0,%1,%2,%3};\n"
        : "+f"(c[0]), "+f"(c[1]), "+f"(c[2]), "+f"(c[3])
        : "r"(a0), "r"(a1), "r"(a2), "r"(a3), "r"(b0), "r"(b1));
}
__device__ __forceinline__ void mma_bf16(float* c,
    unsigned a0, unsigned a1, unsigned a2, unsigned a3,
    unsigned b0, unsigned b1) {
    asm volatile(
        "mma.sync.aligned.m16n8k16.row.col.f32.bf16.bf16.f32 "
        "{%0,%1,%2,%3}, {%4,%5,%6,%7}, {%8,%9}, {%0,%1,%2,%3};\n"
        : "+f"(c[0]), "+f"(c[1]), "+f"(c[2]), "+f"(c[3])
        : "r"(a0), "r"(a1), "r"(a2), "r"(a3), "r"(b0), "r"(b1));
}
__device__ __forceinline__ unsigned sptr(const void* p) {
    return (unsigned)__cvta_generic_to_shared(p);
}
__device__ __forceinline__ void ldsm_x4(unsigned& r0, unsigned& r1, unsigned& r2, unsigned& r3, unsigned a) {
    asm volatile("ldmatrix.sync.aligned.m8n8.x4.shared.b16 {%0,%1,%2,%3}, [%4];"
        : "=r"(r0), "=r"(r1), "=r"(r2), "=r"(r3) : "r"(a));
}
__device__ __forceinline__ void ldsm_x2(unsigned& r0, unsigned& r1, unsigned a) {
    asm volatile("ldmatrix.sync.aligned.m8n8.x2.shared.b16 {%0,%1}, [%2];"
        : "=r"(r0), "=r"(r1) : "r"(a));
}
__device__ __forceinline__ void ldsm_x2t(unsigned& r0, unsigned& r1, unsigned a) {
    asm volatile("ldmatrix.sync.aligned.m8n8.x2.trans.shared.b16 {%0,%1}, [%2];"
        : "=r"(r0), "=r"(r1) : "r"(a));
}
// bf16 hi/lo split of a pair (a->low half, b->high half)
__device__ __forceinline__ void pack2(float a, float b, unsigned& hi, unsigned& lo) {
    __nv_bfloat16 ba = __float2bfloat16(a), bb = __float2bfloat16(b);
    hi = ((unsigned)__bfloat16_as_ushort(bb) << 16) | (unsigned)__bfloat16_as_ushort(ba);
    __nv_bfloat16 la = __float2bfloat16(a - __bfloat162float(ba));
    __nv_bfloat16 lb = __float2bfloat16(b - __bfloat162float(bb));
    lo = ((unsigned)__bfloat16_as_ushort(lb) << 16) | (unsigned)__bfloat16_as_ushort(la);
}

// ---------------------------------------------------------------------------
// K1: three 1024^3 GEMMs via 3-pass bf16 mma (z=0: Q, z=1: K, z=2: V2^T)
// ---------------------------------------------------------------------------
#define K1_AS 1536   // 128*12 b32 per A buffer
#define K1_BS 1088   // 16*68 b32 per B buffer

__global__ void __launch_bounds__(256, 2) k_gemm3(
    const float* __restrict__ roi,
    const float* __restrict__ Wq, const float* __restrict__ bq,
    const float* __restrict__ Wk, const float* __restrict__ bk,
    const float* __restrict__ Wout)
{
    extern __shared__ unsigned smu[];
    unsigned* Ah = smu;
    unsigned* Al = Ah + 2 * K1_AS;
    unsigned* Bh = Al + 2 * K1_AS;
    unsigned* Bl = Bh + 2 * K1_BS;

    const int z = blockIdx.z;
    const int rowBase = blockIdx.y * 128, colBase = blockIdx.x * 128;
    const int tid = threadIdx.x, lane = tid & 31, wid = tid >> 5;
    const int g = lane >> 2, tg = lane & 3;
    const int m_off = (wid >> 2) * 64, n_off = (wid & 3) * 32;
    const float* Bm = (z == 0) ? Wq : (z == 1) ? Wk : Wout;

    float acc[4][4][4] = {};
    const int larow = lane & 15, lcol4 = (lane >> 4) * 4;
    float4 aReg[2], bReg[2];

    {
        const int k0 = 0;
        #pragma unroll
        for (int it = 0; it < 2; it++) {
            int idx = tid + it * 256;
            int r = idx >> 2, c4 = idx & 3;
            aReg[it] = *(const float4*)&roi[(size_t)(rowBase + r) * 1024 + k0 + c4 * 4];
        }
        #pragma unroll
        for (int it = 0; it < 2; it++) {
            int idx = tid + it * 256;
            int kr = idx >> 5, c4 = idx & 31;
            int col = colBase + c4 * 4;
            const float* src;
            if (z < 2) src = &Bm[(size_t)(k0 + kr) * 1024 + col];
            else { int gg = col >> 6, oo = col & 63; src = &Bm[((size_t)gg * 1024 + (k0 + kr)) * 64 + oo]; }
            bReg[it] = *(const float4*)src;
        }
        #pragma unroll
        for (int it = 0; it < 2; it++) {
            int idx = tid + it * 256;
            int r = idx >> 2, c4 = idx & 3;
            unsigned h0, l0, h1, l1;
            pack2(aReg[it].x, aReg[it].y, h0, l0);
            pack2(aReg[it].z, aReg[it].w, h1, l1);
            Ah[r * 12 + c4 * 2] = h0; Ah[r * 12 + c4 * 2 + 1] = h1;
            Al[r * 12 + c4 * 2] = l0; Al[r * 12 + c4 * 2 + 1] = l1;
        }
        #pragma unroll
        for (int it = 0; it < 2; it++) {
            int idx = tid + it * 256;
            int kr = idx >> 5, c4 = idx & 31;
            unsigned h0, l0, h1, l1;
            pack2(bReg[it].x, bReg[it].y, h0, l0);
            pack2(bReg[it].z, bReg[it].w, h1, l1);
            Bh[kr * 68 + c4 * 2] = h0; Bh[kr * 68 + c4 * 2 + 1] = h1;
            Bl[kr * 68 + c4 * 2] = l0; Bl[kr * 68 + c4 * 2 + 1] = l1;
        }
    }
    __syncthreads();

    for (int s = 0; s < 64; s++) {
        const int buf = s & 1;
        if (s < 63) {
            const int k0 = (s + 1) * 16;
            #pragma unroll
            for (int it = 0; it < 2; it++) {
                int idx = tid + it * 256;
                int r = idx >> 2, c4 = idx & 3;
                aReg[it] = *(const float4*)&roi[(size_t)(rowBase + r) * 1024 + k0 + c4 * 4];
            }
            #pragma unroll
            for (int it = 0; it < 2; it++) {
                int idx = tid + it * 256;
                int kr = idx >> 5, c4 = idx & 31;
                int col = colBase + c4 * 4;
                const float* src;
                if (z < 2) src = &Bm[(size_t)(k0 + kr) * 1024 + col];
                else { int gg = col >> 6, oo = col & 63; src = &Bm[((size_t)gg * 1024 + (k0 + kr)) * 64 + oo]; }
                bReg[it] = *(const float4*)src;
            }
        }

        const unsigned* ah_b = Ah + buf * K1_AS;
        const unsigned* al_b = Al + buf * K1_AS;
        const unsigned* bh_b = Bh + buf * K1_BS;
        const unsigned* bl_b = Bl + buf * K1_BS;

        unsigned ah[4][4], al[4][4];
        #pragma unroll
        for (int mt = 0; mt < 4; mt++) {
            const int rb = m_off + mt * 16;
            ldsm_x4(ah[mt][0], ah[mt][1], ah[mt][2], ah[mt][3],
                    sptr(&ah_b[(rb + larow) * 12 + lcol4]));
            ldsm_x4(al[mt][0], al[mt][1], al[mt][2], al[mt][3],
                    sptr(&al_b[(rb + larow) * 12 + lcol4]));
        }
        #pragma unroll
        for (int nt = 0; nt < 4; nt++) {
            const int nbc = (n_off >> 1) + nt * 4;
            unsigned bh0, bh1, bl0, bl1;
            ldsm_x2t(bh0, bh1, sptr(&bh_b[larow * 68 + nbc]));
            ldsm_x2t(bl0, bl1, sptr(&bl_b[larow * 68 + nbc]));
            #pragma unroll
            for (int mt = 0; mt < 4; mt++) {
                mma_bf16(acc[mt][nt], ah[mt][0], ah[mt][1], ah[mt][2], ah[mt][3], bl0, bl1);
                mma_bf16(acc[mt][nt], al[mt][0], al[mt][1], al[mt][2], al[mt][3], bh0, bh1);
                mma_bf16(acc[mt][nt], ah[mt][0], ah[mt][1], ah[mt][2], ah[mt][3], bh0, bh1);
            }
        }

        if (s < 63) {
            unsigned* AhN = Ah + (buf ^ 1) * K1_AS;
            unsigned* AlN = Al + (buf ^ 1) * K1_AS;
            unsigned* BhN = Bh + (buf ^ 1) * K1_BS;
            unsigned* BlN = Bl + (buf ^ 1) * K1_BS;
            #pragma unroll
            for (int it = 0; it < 2; it++) {
                int idx = tid + it * 256;
                int r = idx >> 2, c4 = idx & 3;
                unsigned h0, l0, h1, l1;
                pack2(aReg[it].x, aReg[it].y, h0, l0);
                pack2(aReg[it].z, aReg[it].w, h1, l1);
                AhN[r * 12 + c4 * 2] = h0; AhN[r * 12 + c4 * 2 + 1] = h1;
                AlN[r * 12 + c4 * 2] = l0; AlN[r * 12 + c4 * 2 + 1] = l1;
            }
            #pragma unroll
            for (int it = 0; it < 2; it++) {
                int idx = tid + it * 256;
                int kr = idx >> 5, c4 = idx & 31;
                unsigned h0, l0, h1, l1;
                pack2(bReg[it].x, bReg[it].y, h0, l0);
                pack2(bReg[it].z, bReg[it].w, h1, l1);
                BhN[kr * 68 + c4 * 2] = h0; BhN[kr * 68 + c4 * 2 + 1] = h1;
                BlN[kr * 68 + c4 * 2] = l0; BlN[kr * 68 + c4 * 2 + 1] = l1;
            }
        }
        __syncthreads();
    }

    #pragma unroll
    for (int mt = 0; mt < 4; mt++) {
        #pragma unroll
        for (int nt = 0; nt < 4; nt++) {
            #pragma unroll
            for (int e = 0; e < 4; e++) {
                int row = rowBase + m_off + mt * 16 + g + ((e >= 2) ? 8 : 0);
                int col = colBase + n_off + nt * 8 + 2 * tg + (e & 1);
                float v = acc[mt][nt][e];
                if (z == 0)      g_q[(size_t)row * 1024 + col] = v + bq[col];
                else if (z == 1) g_k[(size_t)row * 1024 + col] = v + bk[col];
                else             g_v2[(size_t)col * 1024 + row] = v;
            }
        }
    }
}

// ---------------------------------------------------------------------------
// K2: PE MLP via tf32 mma (unchanged)
// ---------------------------------------------------------------------------
__global__ void __launch_bounds__(256, 2) k_pe(
    const float* __restrict__ pe,
    const float* __restrict__ W1, const float* __restrict__ b1,
    const float* __restrict__ W2, const float* __restrict__ b2)
{
    extern __shared__ float sm2[];
    float* H    = sm2;
    float* W1sT = H + 17408;
    float* W2sT = W1sT + 4352;
    float* bb1  = W2sT + 1088;
    float* bb2  = bb1 + 64;

    const int tid = threadIdx.x, lane = tid & 31, wid = tid >> 5;
    const int g = lane >> 2, tg = lane & 3;
    const int arow = lane & 15, acolo = (lane >> 4) * 4;
    const int brow = lane & 7, bcolo = ((lane >> 3) & 1) * 4;

    for (int l = tid; l < 4096; l += 256) {
        int k = l >> 6, n = l & 63;
        W1sT[n * 68 + k] = __uint_as_float(f2tf(W1[l]));
    }
    for (int l = tid; l < 1024; l += 256) {
        int k = l >> 4, n = l & 15;
        W2sT[n * 68 + k] = __uint_as_float(f2tf(W2[l]));
    }
    if (tid < 64) bb1[tid] = b1[tid];
    if (tid < 16) bb2[tid] = b2[tid];

    const size_t base = (size_t)blockIdx.x * 256 * 64;
    #pragma unroll
    for (int it = 0; it < 16; it++) {
        int idx = tid + it * 256;
        int r = idx >> 4, c4 = idx & 15;
        float4 v = *(const float4*)&pe[base + (size_t)idx * 4];
        float4 w;
        w.x = __uint_as_float(f2tf(v.x)); w.y = __uint_as_float(f2tf(v.y));
        w.z = __uint_as_float(f2tf(v.z)); w.w = __uint_as_float(f2tf(v.w));
        *(float4*)&H[r * 68 + c4 * 4] = w;
    }
    __syncthreads();

    const int rb0 = wid * 32;
    float acc[2][8][4] = {};
    #pragma unroll
    for (int kt = 0; kt < 8; kt++) {
        const int kb = kt * 8;
        unsigned a[2][4];
        #pragma unroll
        for (int mt = 0; mt < 2; mt++) {
            ldsm_x4(a[mt][0], a[mt][1], a[mt][2], a[mt][3],
                    sptr(&H[(rb0 + mt * 16 + arow) * 68 + kb + acolo]));
        }
        #pragma unroll
        for (int nt = 0; nt < 8; nt++) {
            unsigned b0, b1r;
            ldsm_x2(b0, b1r, sptr(&W1sT[(nt * 8 + brow) * 68 + kb + bcolo]));
            mma_tf32(acc[0][nt], a[0][0], a[0][1], a[0][2], a[0][3], b0, b1r);
            mma_tf32(acc[1][nt], a[1][0], a[1][1], a[1][2], a[1][3], b0, b1r);
        }
    }

    #pragma unroll
    for (int mt = 0; mt < 2; mt++) {
        const int r0 = rb0 + mt * 16 + g;
        #pragma unroll
        for (int nt = 0; nt < 8; nt++) {
            const int col = nt * 8 + 2 * tg;
            float h0 = tanhf(acc[mt][nt][0] + bb1[col]);
            float h1 = tanhf(acc[mt][nt][1] + bb1[col + 1]);
            float h2 = tanhf(acc[mt][nt][2] + bb1[col]);
            float h3 = tanhf(acc[mt][nt][3] + bb1[col + 1]);
            H[r0 * 68 + col]       = __uint_as_float(f2tf(h0));
            H[r0 * 68 + col + 1]   = __uint_as_float(f2tf(h1));
            H[(r0 + 8) * 68 + col]     = __uint_as_float(f2tf(h2));
            H[(r0 + 8) * 68 + col + 1] = __uint_as_float(f2tf(h3));
        }
    }
    __syncwarp();

    float acc2[2][2][4] = {};
    #pragma unroll
    for (int kt = 0; kt < 8; kt++) {
        const int kb = kt * 8;
        unsigned a[2][4];
        #pragma unroll
        for (int mt = 0; mt < 2; mt++) {
            ldsm_x4(a[mt][0], a[mt][1], a[mt][2], a[mt][3],
                    sptr(&H[(rb0 + mt * 16 + arow) * 68 + kb + acolo]));
        }
        #pragma unroll
        for (int nt = 0; nt < 2; nt++) {
            unsigned b0, b1r;
            ldsm_x2(b0, b1r, sptr(&W2sT[(nt * 8 + brow) * 68 + kb + bcolo]));
            mma_tf32(acc2[0][nt], a[0][0], a[0][1], a[0][2], a[0][3], b0, b1r);
            mma_tf32(acc2[1][nt], a[1][0], a[1][1], a[1][2], a[1][3], b0, b1r);
        }
    }

    const int growBase = blockIdx.x * 256;
    const int i = growBase >> 10;
    #pragma unroll
    for (int mt = 0; mt < 2; mt++) {
        #pragma unroll
        for (int nt = 0; nt < 2; nt++) {
            #pragma unroll
            for (int e = 0; e < 4; e++) {
                int grow = growBase + rb0 + mt * 16 + g + ((e >= 2) ? 8 : 0);
                int j = grow & 1023;
                int col = nt * 8 + 2 * tg + (e & 1);
                g_aff[((size_t)i * 16 + col) * 1024 + j] = acc2[mt][nt][e] + bb2[col];
            }
        }
    }
}

// ---------------------------------------------------------------------------
// K3 fused: flash attention with inline aff multiply, bf16 3-pass, P kept in
// registers (S C-fragments re-packed directly as P A-fragments).
// Block: (32 i-rows, group). 8 warps: mw=wid>>2 (m16 tile), nw=wid&3 (j-slice
// of 16 within each 64-j chunk). Partial O reduced across nw at block end.
// smem ~48 KB.
// ---------------------------------------------------------------------------
#define FL_SMEM_U (2 * 1152 + 9216 + 128 + 256 + 32)

__global__ void __launch_bounds__(256) k_flash(
    const float* __restrict__ bout, float* __restrict__ out)
{
    extern __shared__ unsigned smf[];
    unsigned* Qh = smf;              // [32][36]
    unsigned* Ql = Qh + 1152;
    unsigned* KV = Ql + 1152;        // 9216: Kh|Kl|Vh|Vl ; reused as Ored at end
    unsigned* Kh = KV;
    unsigned* Kl = KV + 2304;
    unsigned* Vh = KV + 4608;
    unsigned* Vl = KV + 6912;
    float* Ored    = (float*)KV;           // [4][32][66] = 8448 floats
    float* part_mx = (float*)(KV + 9216);  // [32][4]
    float* part_sm = part_mx + 128;        // [2][32][4]
    float* l_s     = part_sm + 256;        // [32]

    const int gblk = blockIdx.y;
    const int i0 = blockIdx.x * 32;
    const int tid = threadIdx.x, lane = tid & 31, wid = tid >> 5;
    const int g = lane >> 2, tg = lane & 3;
    const int mw = wid >> 2, nw = wid & 3;
    const int mb = mw * 16;
    const int larow = lane & 15, lcol4 = (lane >> 4) * 4;
    const int brow = lane & 7, bcolo = ((lane >> 3) & 1) * 4;

    // Q tile [32 x 64] -> packed bf16 hi/lo
    #pragma unroll
    for (int it = 0; it < 2; it++) {
        int idx = tid + it * 256;
        int r = idx >> 4, c4 = idx & 15;
        float4 qv = *(const float4*)&g_q[(size_t)(i0 + r) * 1024 + gblk * 64 + c4 * 4];
        unsigned h0, l0, h1, l1;
        pack2(qv.x, qv.y, h0, l0); pack2(qv.z, qv.w, h1, l1);
        Qh[r * 36 + c4 * 2] = h0; Qh[r * 36 + c4 * 2 + 1] = h1;
        Ql[r * 36 + c4 * 2] = l0; Ql[r * 36 + c4 * 2 + 1] = l1;
    }
    part_sm[tid] = 0.f;   // 256 entries = 2 bufs x 32 x 4

    float co[8][4] = {};
    float m0 = -1e30f, m1 = -1e30f, l0r = 0.f, l1r = 0.f;

    for (int c = 0; c < 16; c++) {
        const int j0 = c * 64;
        __syncthreads();   // prev chunk consumers done (and Q/part_sm visible on c==0)

        // load K chunk [64 j][64 d] and V chunk [64 o][64 j]
        #pragma unroll
        for (int it = 0; it < 4; it++) {
            int idx = tid + it * 256;
            int r = idx >> 4, c4 = idx & 15;
            float4 kv = *(const float4*)&g_k[(size_t)(j0 + r) * 1024 + gblk * 64 + c4 * 4];
            float4 vv = *(const float4*)&g_v2[(size_t)(gblk * 64 + r) * 1024 + j0 + c4 * 4];
            unsigned h0, l0, h1, l1;
            pack2(kv.x, kv.y, h0, l0); pack2(kv.z, kv.w, h1, l1);
            Kh[r * 36 + c4 * 2] = h0; Kh[r * 36 + c4 * 2 + 1] = h1;
            Kl[r * 36 + c4 * 2] = l0; Kl[r * 36 + c4 * 2 + 1] = l1;
            pack2(vv.x, vv.y, h0, l0); pack2(vv.z, vv.w, h1, l1);
            Vh[r * 36 + c4 * 2] = h0; Vh[r * 36 + c4 * 2 + 1] = h1;
            Vl[r * 36 + c4 * 2] = l0; Vl[r * 36 + c4 * 2 + 1] = l1;
        }
        __syncthreads();

        // S = Q K^T over this warp's j-slice (16 wide), 3-pass bf16
        float cs[2][4] = {};
        #pragma unroll
        for (int kt = 0; kt < 4; kt++) {
            const int kb = kt * 8;
            unsigned ah[4], al[4];
            ldsm_x4(ah[0], ah[1], ah[2], ah[3], sptr(&Qh[(mb + larow) * 36 + kb + lcol4]));
            ldsm_x4(al[0], al[1], al[2], al[3], sptr(&Ql[(mb + larow) * 36 + kb + lcol4]));
            #pragma unroll
            for (int nt = 0; nt < 2; nt++) {
                const int jn = nw * 16 + nt * 8;
                unsigned bh0, bh1, bl0, bl1;
                ldsm_x2(bh0, bh1, sptr(&Kh[(jn + brow) * 36 + kb + bcolo]));
                ldsm_x2(bl0, bl1, sptr(&Kl[(jn + brow) * 36 + kb + bcolo]));
                mma_bf16(cs[nt], ah[0], ah[1], ah[2], ah[3], bl0, bl1);
                mma_bf16(cs[nt], al[0], al[1], al[2], al[3], bh0, bh1);
                mma_bf16(cs[nt], ah[0], ah[1], ah[2], ah[3], bh0, bh1);
            }
        }

        // weighted logits: w = aff * (s/8)
        const int r0g = i0 + mb + g;
        #pragma unroll
        for (int nt = 0; nt < 2; nt++) {
            const int jc = j0 + nw * 16 + nt * 8 + 2 * tg;
            float2 a0 = *(const float2*)&g_aff[((size_t)r0g * 16 + gblk) * 1024 + jc];
            float2 a1 = *(const float2*)&g_aff[((size_t)(r0g + 8) * 16 + gblk) * 1024 + jc];
            cs[nt][0] = cs[nt][0] * 0.125f * a0.x;
            cs[nt][1] = cs[nt][1] * 0.125f * a0.y;
            cs[nt][2] = cs[nt][2] * 0.125f * a1.x;
            cs[nt][3] = cs[nt][3] * 0.125f * a1.y;
        }

        // per-row partial max over this warp's 16 j (reduce across quad)
        float mx0 = fmaxf(fmaxf(cs[0][0], cs[0][1]), fmaxf(cs[1][0], cs[1][1]));
        float mx1 = fmaxf(fmaxf(cs[0][2], cs[0][3]), fmaxf(cs[1][2], cs[1][3]));
        mx0 = fmaxf(mx0, __shfl_xor_sync(0xffffffffu, mx0, 1));
        mx0 = fmaxf(mx0, __shfl_xor_sync(0xffffffffu, mx0, 2));
        mx1 = fmaxf(mx1, __shfl_xor_sync(0xffffffffu, mx1, 1));
        mx1 = fmaxf(mx1, __shfl_xor_sync(0xffffffffu, mx1, 2));
        if (tg == 0) {
            part_mx[(mb + g) * 4 + nw] = mx0;
            part_mx[(mb + g + 8) * 4 + nw] = mx1;
        }
        __syncthreads();

        // all warps: global row max (redundant compute), alpha from register m
        float4 pm0 = *(const float4*)&part_mx[(mb + g) * 4];
        float4 pm1 = *(const float4*)&part_mx[(mb + g + 8) * 4];
        float mn0 = fmaxf(m0, fmaxf(fmaxf(pm0.x, pm0.y), fmaxf(pm0.z, pm0.w)));
        float mn1 = fmaxf(m1, fmaxf(fmaxf(pm1.x, pm1.y), fmaxf(pm1.z, pm1.w)));
        float alpha0 = __expf(m0 - mn0);
        float alpha1 = __expf(m1 - mn1);
        m0 = mn0; m1 = mn1;

        // nw0 warps fold previous chunk's partial sums into register l
        if (nw == 0) {
            const float* smPrev = part_sm + (((c & 1) ^ 1) * 128);
            float4 s0 = *(const float4*)&smPrev[(mb + g) * 4];
            float4 s1 = *(const float4*)&smPrev[(mb + g + 8) * 4];
            l0r = (l0r + s0.x + s0.y + s0.z + s0.w) * alpha0;
            l1r = (l1r + s1.x + s1.y + s1.z + s1.w) * alpha1;
        }

        // p = exp(w - m), partial sums, pack directly into A-fragment regs
        float p00 = __expf(cs[0][0] - mn0), p01 = __expf(cs[0][1] - mn0);
        float p02 = __expf(cs[0][2] - mn1), p03 = __expf(cs[0][3] - mn1);
        float p10 = __expf(cs[1][0] - mn0), p11 = __expf(cs[1][1] - mn0);
        float p12 = __expf(cs[1][2] - mn1), p13 = __expf(cs[1][3] - mn1);
        float su0 = p00 + p01 + p10 + p11;
        float su1 = p02 + p03 + p12 + p13;
        su0 += __shfl_xor_sync(0xffffffffu, su0, 1);
        su0 += __shfl_xor_sync(0xffffffffu, su0, 2);
        su1 += __shfl_xor_sync(0xffffffffu, su1, 1);
        su1 += __shfl_xor_sync(0xffffffffu, su1, 2);
        if (tg == 0) {
            float* smCur = part_sm + ((c & 1) * 128);
            smCur[(mb + g) * 4 + nw] = su0;
            smCur[(mb + g + 8) * 4 + nw] = su1;
        }
        unsigned ph0, ph1, ph2, ph3, pl0, pl1, pl2, pl3;
        pack2(p00, p01, ph0, pl0);   // (row g,   j 2tg..)
        pack2(p02, p03, ph1, pl1);   // (row g+8, j 2tg..)
        pack2(p10, p11, ph2, pl2);   // (row g,   j 2tg+8..)
        pack2(p12, p13, ph3, pl3);   // (row g+8, j 2tg+8..)

        // rescale partial O, then O += P V over this warp's j-slice
        #pragma unroll
        for (int ont = 0; ont < 8; ont++) {
            co[ont][0] *= alpha0; co[ont][1] *= alpha0;
            co[ont][2] *= alpha1; co[ont][3] *= alpha1;
        }
        const int kbv = nw * 8;   // b32 offset of this warp's j-slice in V rows
        #pragma unroll
        for (int ont = 0; ont < 8; ont++) {
            const int ob = ont * 8;
            unsigned bh0, bh1, bl0, bl1;
            ldsm_x2(bh0, bh1, sptr(&Vh[(ob + brow) * 36 + kbv + bcolo]));
            ldsm_x2(bl0, bl1, sptr(&Vl[(ob + brow) * 36 + kbv + bcolo]));
            mma_bf16(co[ont], ph0, ph1, ph2, ph3, bl0, bl1);
            mma_bf16(co[ont], pl0, pl1, pl2, pl3, bh0, bh1);
            mma_bf16(co[ont], ph0, ph1, ph2, ph3, bh0, bh1);
        }
    }

    // final l fold + publish
    if (nw == 0) {
        const float* smLast = part_sm + ((15 & 1) * 128);
        float4 s0 = *(const float4*)&smLast[(mb + g) * 4];
        float4 s1 = *(const float4*)&smLast[(mb + g + 8) * 4];
        l0r += s0.x + s0.y + s0.z + s0.w;
        l1r += s1.x + s1.y + s1.z + s1.w;
        if (tg == 0) { l_s[mb + g] = l0r; l_s[mb + g + 8] = l1r; }
    }
    __syncthreads();   // mma done -> safe to overwrite K/V region with Ored

    // write partial O: Ored[nw][row][o] (stride 66)
    #pragma unroll
    for (int ont = 0; ont < 8; ont++) {
        const int col = ont * 8 + 2 * tg;
        Ored[nw * 2112 + (mb + g) * 66 + col]     = co[ont][0];
        Ored[nw * 2112 + (mb + g) * 66 + col + 1] = co[ont][1];
        Ored[nw * 2112 + (mb + g + 8) * 66 + col]     = co[ont][2];
        Ored[nw * 2112 + (mb + g + 8) * 66 + col + 1] = co[ont][3];
    }
    __syncthreads();

    // reduce across nw, normalize, bias, store
    {
        const int row = tid >> 3, o0 = (tid & 7) * 8;
        const float invl = 1.0f / l_s[row];
        float res[8];
        #pragma unroll
        for (int k = 0; k < 8; k++) {
            const int o = o0 + k;
            float s = Ored[row * 66 + o] + Ored[2112 + row * 66 + o]
                    + Ored[4224 + row * 66 + o] + Ored[6336 + row * 66 + o];
            res[k] = s * invl + bout[gblk * 64 + o];
        }
        float* dst = &out[(size_t)(i0 + row) * 1024 + gblk * 64 + o0];
        *(float4*)dst = make_float4(res[0], res[1], res[2], res[3]);
        *(float4*)(dst + 4) = make_float4(res[4], res[5], res[6], res[7]);
    }
}

// ---------------------------------------------------------------------------
extern "C" void kernel_launch(void* const* d_in, const int* in_sizes, int n_in,
                              void* d_out, int out_size) {
    const float* roi  = (const float*)d_in[0];
    const float* pe   = (const float*)d_in[1];
    const float* W1   = (const float*)d_in[2];
    const float* b1   = (const float*)d_in[3];
    const float* W2   = (const float*)d_in[4];
    const float* b2   = (const float*)d_in[5];
    const float* Wq   = (const float*)d_in[6];
    const float* bq   = (const float*)d_in[7];
    const float* Wk   = (const float*)d_in[8];
    const float* bk   = (const float*)d_in[9];
    const float* Wout = (const float*)d_in[10];
    const float* bout = (const float*)d_in[11];
    float* out = (float*)d_out;

    const int g3_smem = (4 * K1_AS + 4 * K1_BS) * (int)sizeof(unsigned);
    const int pe_smem = (17408 + 4352 + 1088 + 64 + 16) * (int)sizeof(float);
    const int fl_smem = FL_SMEM_U * (int)sizeof(unsigned);
    cudaFuncSetAttribute(k_gemm3, cudaFuncAttributeMaxDynamicSharedMemorySize, g3_smem);
    cudaFuncSetAttribute(k_pe,    cudaFuncAttributeMaxDynamicSharedMemorySize, pe_smem);
    cudaFuncSetAttribute(k_flash, cudaFuncAttributeMaxDynamicSharedMemorySize, fl_smem);

    k_gemm3<<<dim3(8, 8, 3), 256, g3_smem>>>(roi, Wq, bq, Wk, bk, Wout);
    k_pe<<<(Nn * Nn) / 256, 256, pe_smem>>>(pe, W1, b1, W2, b2);
    k_flash<<<dim3(Nn / 32, Gg), 256, fl_smem>>>(bout, out);
}

// round 11
// speedup vs baseline: 1.0566x; 1.0566x over previous
#include <cuda_runtime.h>
#include <cuda_bf16.h>
#include <math.h>

#define Nn 1024
#define Dd 1024
#define Gg 16

// Scratch (allocation-free rule: __device__ globals). Packed bf16 hi/lo pairs.
__device__ unsigned g_qh[Nn * 512], g_ql[Nn * 512];   // q [i][d/2]  (pairs along d)
__device__ unsigned g_kh[Nn * 512], g_kl[Nn * 512];   // k [j][d/2]
__device__ unsigned g_vh[Nn * 512], g_vl[Nn * 512];   // v2 [j][o/2] (pairs along o)
__device__ float g_aff[(size_t)Nn * Gg * Nn];         // aff -> overwritten with weighted logits

__device__ __forceinline__ unsigned f2tf(float x) {
    unsigned u; asm("cvt.rna.tf32.f32 %0, %1;" : "=r"(u) : "f"(x)); return u;
}
__device__ __forceinline__ float ftanh(float x) {
    float y; asm("tanh.approx.f32 %0, %1;" : "=f"(y) : "f"(x)); return y;
}
__device__ __forceinline__ void mma_tf32(float* c,
    unsigned a0, unsigned a1, unsigned a2, unsigned a3,
    unsigned b0, unsigned b1) {
    asm volatile(
        "mma.sync.aligned.m16n8k8.row.col.f32.tf32.tf32.f32 "
        "{%0,%1,%2,%3}, {%4,%5,%6,%7}, {%8,%9}, {%0,%1,%2,%3};\n"
        : "+f"(c[0]), "+f"(c[1]), "+f"(c[2]), "+f"(c[3])
        : "r"(a0), "r"(a1), "r"(a2), "r"(a3), "r"(b0), "r"(b1));
}
__device__ __forceinline__ void mma_bf16(float* c,
    unsigned a0, unsigned a1, unsigned a2, unsigned a3,
    unsigned b0, unsigned b1) {
    asm volatile(
        "mma.sync.aligned.m16n8k16.row.col.f32.bf16.bf16.f32 "
        "{%0,%1,%2,%3}, {%4,%5,%6,%7}, {%8,%9}, {%0,%1,%2,%3};\n"
        : "+f"(c[0]), "+f"(c[1]), "+f"(c[2]), "+f"(c[3])
        : "r"(a0), "r"(a1), "r"(a2), "r"(a3), "r"(b0), "r"(b1));
}
__device__ __forceinline__ unsigned sptr(const void* p) {
    return (unsigned)__cvta_generic_to_shared(p);
}
__device__ __forceinline__ void ldsm_x4(unsigned& r0, unsigned& r1, unsigned& r2, unsigned& r3, unsigned a) {
    asm volatile("ldmatrix.sync.aligned.m8n8.x4.shared.b16 {%0,%1,%2,%3}, [%4];"
        : "=r"(r0), "=r"(r1), "=r"(r2), "=r"(r3) : "r"(a));
}
__device__ __forceinline__ void ldsm_x2(unsigned& r0, unsigned& r1, unsigned a) {
    asm volatile("ldmatrix.sync.aligned.m8n8.x2.shared.b16 {%0,%1}, [%2];"
        : "=r"(r0), "=r"(r1) : "r"(a));
}
__device__ __forceinline__ void ldsm_x2t(unsigned& r0, unsigned& r1, unsigned a) {
    asm volatile("ldmatrix.sync.aligned.m8n8.x2.trans.shared.b16 {%0,%1}, [%2];"
        : "=r"(r0), "=r"(r1) : "r"(a));
}
// bf16 hi/lo split of a pair (a->low half, b->high half)
__device__ __forceinline__ void pack2(float a, float b, unsigned& hi, unsigned& lo) {
    __nv_bfloat16 ba = __float2bfloat16(a), bb = __float2bfloat16(b);
    hi = ((unsigned)__bfloat16_as_ushort(bb) << 16) | (unsigned)__bfloat16_as_ushort(ba);
    __nv_bfloat16 la = __float2bfloat16(a - __bfloat162float(ba));
    __nv_bfloat16 lb = __float2bfloat16(b - __bfloat162float(bb));
    lo = ((unsigned)__bfloat16_as_ushort(lb) << 16) | (unsigned)__bfloat16_as_ushort(la);
}

// ---------------------------------------------------------------------------
// K1: three 1024^3 GEMMs via 3-pass bf16 mma (z=0: Q, z=1: K, z=2: V2)
// Epilogue writes packed bf16 hi/lo directly.
// ---------------------------------------------------------------------------
#define K1_AS 1536   // 128*12 b32 per A buffer
#define K1_BS 1088   // 16*68 b32 per B buffer

__global__ void __launch_bounds__(256, 2) k_gemm3(
    const float* __restrict__ roi,
    const float* __restrict__ Wq, const float* __restrict__ bq,
    const float* __restrict__ Wk, const float* __restrict__ bk,
    const float* __restrict__ Wout)
{
    extern __shared__ unsigned smu[];
    unsigned* Ah = smu;
    unsigned* Al = Ah + 2 * K1_AS;
    unsigned* Bh = Al + 2 * K1_AS;
    unsigned* Bl = Bh + 2 * K1_BS;

    const int z = blockIdx.z;
    const int rowBase = blockIdx.y * 128, colBase = blockIdx.x * 128;
    const int tid = threadIdx.x, lane = tid & 31, wid = tid >> 5;
    const int g = lane >> 2, tg = lane & 3;
    const int m_off = (wid >> 2) * 64, n_off = (wid & 3) * 32;
    const float* Bm = (z == 0) ? Wq : (z == 1) ? Wk : Wout;

    float acc[4][4][4] = {};
    const int larow = lane & 15, lcol4 = (lane >> 4) * 4;
    float4 aReg[2], bReg[2];

    {
        const int k0 = 0;
        #pragma unroll
        for (int it = 0; it < 2; it++) {
            int idx = tid + it * 256;
            int r = idx >> 2, c4 = idx & 3;
            aReg[it] = *(const float4*)&roi[(size_t)(rowBase + r) * 1024 + k0 + c4 * 4];
        }
        #pragma unroll
        for (int it = 0; it < 2; it++) {
            int idx = tid + it * 256;
            int kr = idx >> 5, c4 = idx & 31;
            int col = colBase + c4 * 4;
            const float* src;
            if (z < 2) src = &Bm[(size_t)(k0 + kr) * 1024 + col];
            else { int gg = col >> 6, oo = col & 63; src = &Bm[((size_t)gg * 1024 + (k0 + kr)) * 64 + oo]; }
            bReg[it] = *(const float4*)src;
        }
        #pragma unroll
        for (int it = 0; it < 2; it++) {
            int idx = tid + it * 256;
            int r = idx >> 2, c4 = idx & 3;
            unsigned h0, l0, h1, l1;
            pack2(aReg[it].x, aReg[it].y, h0, l0);
            pack2(aReg[it].z, aReg[it].w, h1, l1);
            Ah[r * 12 + c4 * 2] = h0; Ah[r * 12 + c4 * 2 + 1] = h1;
            Al[r * 12 + c4 * 2] = l0; Al[r * 12 + c4 * 2 + 1] = l1;
        }
        #pragma unroll
        for (int it = 0; it < 2; it++) {
            int idx = tid + it * 256;
            int kr = idx >> 5, c4 = idx & 31;
            unsigned h0, l0, h1, l1;
            pack2(bReg[it].x, bReg[it].y, h0, l0);
            pack2(bReg[it].z, bReg[it].w, h1, l1);
            Bh[kr * 68 + c4 * 2] = h0; Bh[kr * 68 + c4 * 2 + 1] = h1;
            Bl[kr * 68 + c4 * 2] = l0; Bl[kr * 68 + c4 * 2 + 1] = l1;
        }
    }
    __syncthreads();

    for (int s = 0; s < 64; s++) {
        const int buf = s & 1;
        if (s < 63) {
            const int k0 = (s + 1) * 16;
            #pragma unroll
            for (int it = 0; it < 2; it++) {
                int idx = tid + it * 256;
                int r = idx >> 2, c4 = idx & 3;
                aReg[it] = *(const float4*)&roi[(size_t)(rowBase + r) * 1024 + k0 + c4 * 4];
            }
            #pragma unroll
            for (int it = 0; it < 2; it++) {
                int idx = tid + it * 256;
                int kr = idx >> 5, c4 = idx & 31;
                int col = colBase + c4 * 4;
                const float* src;
                if (z < 2) src = &Bm[(size_t)(k0 + kr) * 1024 + col];
                else { int gg = col >> 6, oo = col & 63; src = &Bm[((size_t)gg * 1024 + (k0 + kr)) * 64 + oo]; }
                bReg[it] = *(const float4*)src;
            }
        }

        const unsigned* ah_b = Ah + buf * K1_AS;
        const unsigned* al_b = Al + buf * K1_AS;
        const unsigned* bh_b = Bh + buf * K1_BS;
        const unsigned* bl_b = Bl + buf * K1_BS;

        unsigned ah[4][4], al[4][4];
        #pragma unroll
        for (int mt = 0; mt < 4; mt++) {
            const int rb = m_off + mt * 16;
            ldsm_x4(ah[mt][0], ah[mt][1], ah[mt][2], ah[mt][3],
                    sptr(&ah_b[(rb + larow) * 12 + lcol4]));
            ldsm_x4(al[mt][0], al[mt][1], al[mt][2], al[mt][3],
                    sptr(&al_b[(rb + larow) * 12 + lcol4]));
        }
        #pragma unroll
        for (int nt = 0; nt < 4; nt++) {
            const int nbc = (n_off >> 1) + nt * 4;
            unsigned bh0, bh1, bl0, bl1;
            ldsm_x2t(bh0, bh1, sptr(&bh_b[larow * 68 + nbc]));
            ldsm_x2t(bl0, bl1, sptr(&bl_b[larow * 68 + nbc]));
            #pragma unroll
            for (int mt = 0; mt < 4; mt++) {
                mma_bf16(acc[mt][nt], ah[mt][0], ah[mt][1], ah[mt][2], ah[mt][3], bl0, bl1);
                mma_bf16(acc[mt][nt], al[mt][0], al[mt][1], al[mt][2], al[mt][3], bh0, bh1);
                mma_bf16(acc[mt][nt], ah[mt][0], ah[mt][1], ah[mt][2], ah[mt][3], bh0, bh1);
            }
        }

        if (s < 63) {
            unsigned* AhN = Ah + (buf ^ 1) * K1_AS;
            unsigned* AlN = Al + (buf ^ 1) * K1_AS;
            unsigned* BhN = Bh + (buf ^ 1) * K1_BS;
            unsigned* BlN = Bl + (buf ^ 1) * K1_BS;
            #pragma unroll
            for (int it = 0; it < 2; it++) {
                int idx = tid + it * 256;
                int r = idx >> 2, c4 = idx & 3;
                unsigned h0, l0, h1, l1;
                pack2(aReg[it].x, aReg[it].y, h0, l0);
                pack2(aReg[it].z, aReg[it].w, h1, l1);
                AhN[r * 12 + c4 * 2] = h0; AhN[r * 12 + c4 * 2 + 1] = h1;
                AlN[r * 12 + c4 * 2] = l0; AlN[r * 12 + c4 * 2 + 1] = l1;
            }
            #pragma unroll
            for (int it = 0; it < 2; it++) {
                int idx = tid + it * 256;
                int kr = idx >> 5, c4 = idx & 31;
                unsigned h0, l0, h1, l1;
                pack2(bReg[it].x, bReg[it].y, h0, l0);
                pack2(bReg[it].z, bReg[it].w, h1, l1);
                BhN[kr * 68 + c4 * 2] = h0; BhN[kr * 68 + c4 * 2 + 1] = h1;
                BlN[kr * 68 + c4 * 2] = l0; BlN[kr * 68 + c4 * 2 + 1] = l1;
            }
        }
        __syncthreads();
    }

    // epilogue: add bias, pack to bf16 hi/lo, store u32 pairs
    #pragma unroll
    for (int mt = 0; mt < 4; mt++) {
        #pragma unroll
        for (int nt = 0; nt < 4; nt++) {
            const int row = rowBase + m_off + mt * 16 + g;
            const int col = colBase + n_off + nt * 8 + 2 * tg;
            const size_t p0 = (size_t)row * 512 + (col >> 1);
            const size_t p1 = (size_t)(row + 8) * 512 + (col >> 1);
            float v0 = acc[mt][nt][0], v1 = acc[mt][nt][1];
            float v2 = acc[mt][nt][2], v3 = acc[mt][nt][3];
            unsigned h, l;
            if (z == 0) {
                float b0 = bq[col], b1 = bq[col + 1];
                pack2(v0 + b0, v1 + b1, h, l); g_qh[p0] = h; g_ql[p0] = l;
                pack2(v2 + b0, v3 + b1, h, l); g_qh[p1] = h; g_ql[p1] = l;
            } else if (z == 1) {
                float b0 = bk[col], b1 = bk[col + 1];
                pack2(v0 + b0, v1 + b1, h, l); g_kh[p0] = h; g_kl[p0] = l;
                pack2(v2 + b0, v3 + b1, h, l); g_kh[p1] = h; g_kl[p1] = l;
            } else {
                pack2(v0, v1, h, l); g_vh[p0] = h; g_vl[p0] = l;
                pack2(v2, v3, h, l); g_vh[p1] = h; g_vl[p1] = l;
            }
        }
    }
}

// ---------------------------------------------------------------------------
// K2: PE MLP via tf32 mma; tanh.approx for the activation.
// ---------------------------------------------------------------------------
__global__ void __launch_bounds__(256, 2) k_pe(
    const float* __restrict__ pe,
    const float* __restrict__ W1, const float* __restrict__ b1,
    const float* __restrict__ W2, const float* __restrict__ b2)
{
    extern __shared__ float sm2[];
    float* H    = sm2;
    float* W1sT = H + 17408;
    float* W2sT = W1sT + 4352;
    float* bb1  = W2sT + 1088;
    float* bb2  = bb1 + 64;

    const int tid = threadIdx.x, lane = tid & 31, wid = tid >> 5;
    const int g = lane >> 2, tg = lane & 3;
    const int arow = lane & 15, acolo = (lane >> 4) * 4;
    const int brow = lane & 7, bcolo = ((lane >> 3) & 1) * 4;

    for (int l = tid; l < 4096; l += 256) {
        int k = l >> 6, n = l & 63;
        W1sT[n * 68 + k] = __uint_as_float(f2tf(W1[l]));
    }
    for (int l = tid; l < 1024; l += 256) {
        int k = l >> 4, n = l & 15;
        W2sT[n * 68 + k] = __uint_as_float(f2tf(W2[l]));
    }
    if (tid < 64) bb1[tid] = b1[tid];
    if (tid < 16) bb2[tid] = b2[tid];

    const size_t base = (size_t)blockIdx.x * 256 * 64;
    #pragma unroll
    for (int it = 0; it < 16; it++) {
        int idx = tid + it * 256;
        int r = idx >> 4, c4 = idx & 15;
        float4 v = *(const float4*)&pe[base + (size_t)idx * 4];
        float4 w;
        w.x = __uint_as_float(f2tf(v.x)); w.y = __uint_as_float(f2tf(v.y));
        w.z = __uint_as_float(f2tf(v.z)); w.w = __uint_as_float(f2tf(v.w));
        *(float4*)&H[r * 68 + c4 * 4] = w;
    }
    __syncthreads();

    const int rb0 = wid * 32;
    float acc[2][8][4] = {};
    #pragma unroll
    for (int kt = 0; kt < 8; kt++) {
        const int kb = kt * 8;
        unsigned a[2][4];
        #pragma unroll
        for (int mt = 0; mt < 2; mt++) {
            ldsm_x4(a[mt][0], a[mt][1], a[mt][2], a[mt][3],
                    sptr(&H[(rb0 + mt * 16 + arow) * 68 + kb + acolo]));
        }
        #pragma unroll
        for (int nt = 0; nt < 8; nt++) {
            unsigned b0, b1r;
            ldsm_x2(b0, b1r, sptr(&W1sT[(nt * 8 + brow) * 68 + kb + bcolo]));
            mma_tf32(acc[0][nt], a[0][0], a[0][1], a[0][2], a[0][3], b0, b1r);
            mma_tf32(acc[1][nt], a[1][0], a[1][1], a[1][2], a[1][3], b0, b1r);
        }
    }

    #pragma unroll
    for (int mt = 0; mt < 2; mt++) {
        const int r0 = rb0 + mt * 16 + g;
        #pragma unroll
        for (int nt = 0; nt < 8; nt++) {
            const int col = nt * 8 + 2 * tg;
            float h0 = ftanh(acc[mt][nt][0] + bb1[col]);
            float h1 = ftanh(acc[mt][nt][1] + bb1[col + 1]);
            float h2 = ftanh(acc[mt][nt][2] + bb1[col]);
            float h3 = ftanh(acc[mt][nt][3] + bb1[col + 1]);
            H[r0 * 68 + col]       = __uint_as_float(f2tf(h0));
            H[r0 * 68 + col + 1]   = __uint_as_float(f2tf(h1));
            H[(r0 + 8) * 68 + col]     = __uint_as_float(f2tf(h2));
            H[(r0 + 8) * 68 + col + 1] = __uint_as_float(f2tf(h3));
        }
    }
    __syncwarp();

    float acc2[2][2][4] = {};
    #pragma unroll
    for (int kt = 0; kt < 8; kt++) {
        const int kb = kt * 8;
        unsigned a[2][4];
        #pragma unroll
        for (int mt = 0; mt < 2; mt++) {
            ldsm_x4(a[mt][0], a[mt][1], a[mt][2], a[mt][3],
                    sptr(&H[(rb0 + mt * 16 + arow) * 68 + kb + acolo]));
        }
        #pragma unroll
        for (int nt = 0; nt < 2; nt++) {
            unsigned b0, b1r;
            ldsm_x2(b0, b1r, sptr(&W2sT[(nt * 8 + brow) * 68 + kb + bcolo]));
            mma_tf32(acc2[0][nt], a[0][0], a[0][1], a[0][2], a[0][3], b0, b1r);
            mma_tf32(acc2[1][nt], a[1][0], a[1][1], a[1][2], a[1][3], b0, b1r);
        }
    }

    const int growBase = blockIdx.x * 256;
    const int i = growBase >> 10;
    #pragma unroll
    for (int mt = 0; mt < 2; mt++) {
        #pragma unroll
        for (int nt = 0; nt < 2; nt++) {
            #pragma unroll
            for (int e = 0; e < 4; e++) {
                int grow = growBase + rb0 + mt * 16 + g + ((e >= 2) ? 8 : 0);
                int j = grow & 1023;
                int col = nt * 8 + 2 * tg + (e & 1);
                g_aff[((size_t)i * 16 + col) * 1024 + j] = acc2[mt][nt][e] + bb2[col];
            }
        }
    }
}

// ---------------------------------------------------------------------------
// K3a: weighted logits W = aff * (Q K^T / 8) in place into g_aff. bf16 3-pass.
// Staging is pure u32 copies from packed producer arrays.
// ---------------------------------------------------------------------------
#define LGT_SMEM_U (4 * 2304)

__global__ void __launch_bounds__(256) k_logits()
{
    extern __shared__ unsigned smlu[];
    unsigned* Qh = smlu;          // [64][36]
    unsigned* Ql = Qh + 2304;
    unsigned* Kh = Ql + 2304;
    unsigned* Kl = Kh + 2304;

    const int gblk = blockIdx.z;
    const int i0 = blockIdx.y * 64, j0 = blockIdx.x * 64;
    const int tid = threadIdx.x, lane = tid & 31, wid = tid >> 5;
    const int g = lane >> 2, tg = lane & 3;
    const int mb = (wid >> 1) * 16, nw = wid & 1;
    const int larow = lane & 15, lcol4 = (lane >> 4) * 4;
    const int brow = lane & 7, bcolo = ((lane >> 3) & 1) * 4;

    #pragma unroll
    for (int it = 0; it < 2; it++) {
        int idx = tid + it * 256;
        int r = idx >> 3, c4 = (idx & 7) * 4;
        const size_t gi = (size_t)(i0 + r) * 512 + gblk * 32 + c4;
        const size_t gj = (size_t)(j0 + r) * 512 + gblk * 32 + c4;
        *(uint4*)&Qh[r * 36 + c4] = *(const uint4*)&g_qh[gi];
        *(uint4*)&Ql[r * 36 + c4] = *(const uint4*)&g_ql[gi];
        *(uint4*)&Kh[r * 36 + c4] = *(const uint4*)&g_kh[gj];
        *(uint4*)&Kl[r * 36 + c4] = *(const uint4*)&g_kl[gj];
    }
    __syncthreads();

    float cs[4][4] = {};
    #pragma unroll
    for (int kt = 0; kt < 4; kt++) {
        const int kb = kt * 8;
        unsigned ah[4], al[4];
        ldsm_x4(ah[0], ah[1], ah[2], ah[3], sptr(&Qh[(mb + larow) * 36 + kb + lcol4]));
        ldsm_x4(al[0], al[1], al[2], al[3], sptr(&Ql[(mb + larow) * 36 + kb + lcol4]));
        #pragma unroll
        for (int nt = 0; nt < 4; nt++) {
            const int nb = nw * 32 + nt * 8;
            unsigned bh0, bh1, bl0, bl1;
            ldsm_x2(bh0, bh1, sptr(&Kh[(nb + brow) * 36 + kb + bcolo]));
            ldsm_x2(bl0, bl1, sptr(&Kl[(nb + brow) * 36 + kb + bcolo]));
            mma_bf16(cs[nt], ah[0], ah[1], ah[2], ah[3], bl0, bl1);
            mma_bf16(cs[nt], al[0], al[1], al[2], al[3], bh0, bh1);
            mma_bf16(cs[nt], ah[0], ah[1], ah[2], ah[3], bh0, bh1);
        }
    }

    #pragma unroll
    for (int nt = 0; nt < 4; nt++) {
        const int col = nw * 32 + nt * 8 + 2 * tg;
        const int r0 = mb + g;
        float* p0 = &g_aff[(((size_t)(i0 + r0)) * 16 + gblk) * 1024 + j0 + col];
        float* p1 = &g_aff[(((size_t)(i0 + r0 + 8)) * 16 + gblk) * 1024 + j0 + col];
        float2 a0 = *(const float2*)p0;
        float2 a1 = *(const float2*)p1;
        *(float2*)p0 = make_float2(cs[nt][0] * 0.125f * a0.x, cs[nt][1] * 0.125f * a0.y);
        *(float2*)p1 = make_float2(cs[nt][2] * 0.125f * a1.x, cs[nt][3] * 0.125f * a1.y);
    }
}

// ---------------------------------------------------------------------------
// K3b: online softmax over W + 3-pass bf16 P@V. V staged as pure u32 copies
// from packed [j][o/2] arrays; B-fragments via ldmatrix.trans.
// ---------------------------------------------------------------------------
#define AT2_SMEM_U (2 * 2304 + 2 * 1152 + 96)

__global__ void __launch_bounds__(256) k_attn2(
    const float* __restrict__ bout, float* __restrict__ out)
{
    extern __shared__ unsigned smau[];
    unsigned* Vh = smau;           // [j=64][36] (o-pairs 0..31)
    unsigned* Vl = Vh + 2304;
    unsigned* Ph = Vl + 2304;      // [i=32][36] (j-pairs)
    unsigned* Pl = Ph + 1152;
    float* m_s  = (float*)(Pl + 1152);   // [32]
    float* l_s  = m_s + 32;
    float* al_s = l_s + 32;

    const int gblk = blockIdx.y;
    const int i0 = blockIdx.x * 32;
    const int tid = threadIdx.x, lane = tid & 31, wid = tid >> 5;
    const int g = lane >> 2, tg = lane & 3;
    const int mb = (wid >> 2) * 16, nw = wid & 3;
    const int larow = lane & 15, lcol4 = (lane >> 4) * 4;

    if (tid < 32) { m_s[tid] = -1e30f; l_s[tid] = 0.f; }

    float co[2][4] = {};

    for (int c = 0; c < 16; c++) {
        const int j0 = c * 64;
        __syncthreads();   // V/P free; stats visible on c==0

        // V chunk: copy packed [j][o-pairs]
        #pragma unroll
        for (int it = 0; it < 2; it++) {
            int idx = tid + it * 256;
            int r = idx >> 3, c4 = (idx & 7) * 4;
            const size_t gv = (size_t)(j0 + r) * 512 + gblk * 32 + c4;
            *(uint4*)&Vh[r * 36 + c4] = *(const uint4*)&g_vh[gv];
            *(uint4*)&Vl[r * 36 + c4] = *(const uint4*)&g_vl[gv];
        }

        // online softmax: warp w owns rows 4w..4w+3 (W read coalesced)
        #pragma unroll
        for (int rr = 0; rr < 4; rr++) {
            const int row = wid * 4 + rr;
            float2 w2 = *(const float2*)&g_aff[(((size_t)(i0 + row)) * 16 + gblk) * 1024 + j0 + 2 * lane];
            float s0 = w2.x, s1 = w2.y;
            float mx = fmaxf(s0, s1);
            #pragma unroll
            for (int o = 16; o; o >>= 1) mx = fmaxf(mx, __shfl_xor_sync(0xffffffffu, mx, o));
            float mold = m_s[row];
            float mnew = fmaxf(mold, mx);
            float p0 = __expf(s0 - mnew), p1 = __expf(s1 - mnew);
            float su = p0 + p1;
            #pragma unroll
            for (int o = 16; o; o >>= 1) su += __shfl_xor_sync(0xffffffffu, su, o);
            if (lane == 0) {
                float alpha = __expf(mold - mnew);
                m_s[row] = mnew;
                al_s[row] = alpha;
                l_s[row] = l_s[row] * alpha + su;
            }
            unsigned ph, pl;
            pack2(p0, p1, ph, pl);
            Ph[row * 36 + lane] = ph;
            Pl[row * 36 + lane] = pl;
        }
        __syncthreads();

        // O = diag(alpha) O + P V   (3-pass bf16)
        {
            float a0 = al_s[mb + g], a1 = al_s[mb + g + 8];
            #pragma unroll
            for (int nt = 0; nt < 2; nt++) {
                co[nt][0] *= a0; co[nt][1] *= a0;
                co[nt][2] *= a1; co[nt][3] *= a1;
            }
            #pragma unroll
            for (int kt = 0; kt < 4; kt++) {
                const int kb = kt * 8;        // j-pair offset for P
                const int jb = kt * 16;       // j-row offset for V
                unsigned ah[4], al[4];
                ldsm_x4(ah[0], ah[1], ah[2], ah[3], sptr(&Ph[(mb + larow) * 36 + kb + lcol4]));
                ldsm_x4(al[0], al[1], al[2], al[3], sptr(&Pl[(mb + larow) * 36 + kb + lcol4]));
                #pragma unroll
                for (int nt = 0; nt < 2; nt++) {
                    const int vcol = nw * 8 + nt * 4;   // o-pair column
                    unsigned bh0, bh1, bl0, bl1;
                    ldsm_x2t(bh0, bh1, sptr(&Vh[(jb + larow) * 36 + vcol]));
                    ldsm_x2t(bl0, bl1, sptr(&Vl[(jb + larow) * 36 + vcol]));
                    mma_bf16(co[nt], ah[0], ah[1], ah[2], ah[3], bl0, bl1);
                    mma_bf16(co[nt], al[0], al[1], al[2], al[3], bh0, bh1);
                    mma_bf16(co[nt], ah[0], ah[1], ah[2], ah[3], bh0, bh1);
                }
            }
        }
    }
    __syncthreads();

    {
        float inv0 = 1.0f / l_s[mb + g];
        float inv1 = 1.0f / l_s[mb + g + 8];
        #pragma unroll
        for (int nt = 0; nt < 2; nt++) {
            const int cl = nw * 16 + nt * 8 + 2 * tg;
            const int col = gblk * 64 + cl;
            float b0 = bout[col], b1 = bout[col + 1];
            int r0 = i0 + mb + g;
            *(float2*)&out[(size_t)r0 * 1024 + col] =
                make_float2(co[nt][0] * inv0 + b0, co[nt][1] * inv0 + b1);
            *(float2*)&out[(size_t)(r0 + 8) * 1024 + col] =
                make_float2(co[nt][2] * inv1 + b0, co[nt][3] * inv1 + b1);
        }
    }
}

// ---------------------------------------------------------------------------
extern "C" void kernel_launch(void* const* d_in, const int* in_sizes, int n_in,
                              void* d_out, int out_size) {
    const float* roi  = (const float*)d_in[0];
    const float* pe   = (const float*)d_in[1];
    const float* W1   = (const float*)d_in[2];
    const float* b1   = (const float*)d_in[3];
    const float* W2   = (const float*)d_in[4];
    const float* b2   = (const float*)d_in[5];
    const float* Wq   = (const float*)d_in[6];
    const float* bq   = (const float*)d_in[7];
    const float* Wk   = (const float*)d_in[8];
    const float* bk   = (const float*)d_in[9];
    const float* Wout = (const float*)d_in[10];
    const float* bout = (const float*)d_in[11];
    float* out = (float*)d_out;

    const int g3_smem = (4 * K1_AS + 4 * K1_BS) * (int)sizeof(unsigned);
    const int pe_smem = (17408 + 4352 + 1088 + 64 + 16) * (int)sizeof(float);
    const int lg_smem = LGT_SMEM_U * (int)sizeof(unsigned);
    const int at_smem = AT2_SMEM_U * (int)sizeof(unsigned);
    cudaFuncSetAttribute(k_gemm3,  cudaFuncAttributeMaxDynamicSharedMemorySize, g3_smem);
    cudaFuncSetAttribute(k_pe,     cudaFuncAttributeMaxDynamicSharedMemorySize, pe_smem);
    cudaFuncSetAttribute(k_logits, cudaFuncAttributeMaxDynamicSharedMemorySize, lg_smem);
    cudaFuncSetAttribute(k_attn2,  cudaFuncAttributeMaxDynamicSharedMemorySize, at_smem);

    k_gemm3<<<dim3(8, 8, 3), 256, g3_smem>>>(roi, Wq, bq, Wk, bk, Wout);
    k_pe<<<(Nn * Nn) / 256, 256, pe_smem>>>(pe, W1, b1, W2, b2);
    k_logits<<<dim3(16, 16, 16), 256, lg_smem>>>();
    k_attn2<<<dim3(Nn / 32, Gg), 256, at_smem>>>(bout, out);
}